// round 15
// baseline (speedup 1.0000x reference)
#include <cuda_runtime.h>
#include <cuda_fp16.h>

// DigitCaps routing:
//   x [128,1024,16], W [1,16,1024,16,16], B [16,1,1024] -> out [128,16,16] (fp32)
// Measured split (R14): k1 ~45.7us, k2a 29.8us, usum ~5.5us, k2b 5us.
// R15: k2a rewritten register-resident (no smem u_hat tile).

#define BATCH  128
#define NCAPS  16
#define INCAPS 1024
#define DIMC   16
#define COEF   0.25f

#define K1_CB     8
#define K1_NCBLK  128
#define K1_NP     4      // n per CTA
#define K2_CT     32
#define K2_SPLIT  16
#define K2_TILES  2      // 1024 / (32*16)

#define RED_STRIDE 289   // u32 row stride for red[.][c_loc][...]
#define XS_STRIDE  132   // float row stride for xs[b_loc][...] (128 + 4 pad)

// k1 dynamic smem layout (bytes)
#define K1_WS_BYTES   (K1_NP * 2048 * 4)            // 32768
#define K1_XS_BYTES   (32 * XS_STRIDE * 4)          // 16896
#define K1_RED_BYTES  (2 * 8 * RED_STRIDE * 4)      // 18496
#define K1_SMEM_BYTES (K1_WS_BYTES + K1_XS_BYTES + K1_RED_BYTES)  // 68160

typedef unsigned long long u64;
typedef unsigned int u32;

__device__ __forceinline__ u64 f2fma(u64 a, u64 b, u64 c) {
    u64 d;
    asm("fma.rn.f32x2 %0, %1, %2, %3;" : "=l"(d) : "l"(a), "l"(b), "l"(c));
    return d;
}
__device__ __forceinline__ u64 f2dup(float x) {
    u64 d;
    asm("mov.b64 %0, {%1, %1};" : "=l"(d) : "f"(x));
    return d;
}
__device__ __forceinline__ u32 h2_bits(__half2 h) {
    union { __half2 h; u32 u; } cv;
    cv.h = h;
    return cv.u;
}

// scratch
__device__ __half g_uhat[(size_t)BATCH * NCAPS * INCAPS * DIMC];    // [b][n][c][d] fp16, 64 MB
__device__ float  g_part[(size_t)K1_NCBLK * BATCH * NCAPS * DIMC];  // [cblk][b][n*16+d], 16 MB
__device__ float  g_us2[(size_t)8 * BATCH * NCAPS * DIMC];          // [cs8][b][nd], 1 MB
__device__ float  g_usum[(size_t)BATCH * NCAPS * DIMC];             // 128 KB
__device__ float  g_spart[(size_t)K2_SPLIT * BATCH * NCAPS * DIMC]; // 2 MB

// ---------------------------------------------------------------------------
// Kernel 1 (unchanged from R14): grid (128 cblk, 4 ngrp), 256 threads.
// ---------------------------------------------------------------------------
__global__ __launch_bounds__(256, 2) void k1_uhat(const float* __restrict__ x,
                                                  const float* __restrict__ W) {
    extern __shared__ char smem_raw[];
    float* ws  = (float*)smem_raw;                               // [nn][cl][i][d]
    float* xs  = (float*)(smem_raw + K1_WS_BYTES);               // staging
    u32*   red = (u32*)(smem_raw + K1_WS_BYTES + K1_XS_BYTES);   // [hf][cl][l*9+dp]

    const int t = threadIdx.x;
    const int w = t >> 5;
    const int l = t & 31;
    const int cblk   = blockIdx.x;
    const int n_base = blockIdx.y * K1_NP;
    const int c0     = cblk * K1_CB;

    const float4* Wg4 = (const float4*)W;
#pragma unroll
    for (int k = 0; k < 8; k++) {
        int idx4 = t + 256 * k;
        int nn  = idx4 >> 9;
        int rem = idx4 & 511;
        float4 v = Wg4[(size_t)(n_base + nn) * 65536 + c0 * 64 + rem];
        int cl = rem >> 6;
        int d  = (rem >> 2) & 15;
        int i0 = (rem & 3) * 4;
        float* wb = ws + nn * 2048 + cl * 256;
        wb[(i0 + 0) * 16 + d] = v.x;
        wb[(i0 + 1) * 16 + d] = v.y;
        wb[(i0 + 2) * 16 + d] = v.z;
        wb[(i0 + 3) * 16 + d] = v.w;
    }

    const float4* xg4 = (const float4*)x;
    uint4* ug = (uint4*)g_uhat;

    float4 P[4];
#pragma unroll
    for (int k = 0; k < 4; k++) {
        int q = t + 256 * k;
        P[k] = xg4[(q >> 5) * 4096 + c0 * 4 + (q & 31)];
    }

    float XA[16], XB[16];

#pragma unroll
    for (int p = 0; p < 2; p++) {
        const int b0 = p * 64;

#pragma unroll
        for (int k = 0; k < 4; k++) {
            int q = t + 256 * k;
            *(float4*)&xs[(q >> 5) * XS_STRIDE + (q & 31) * 4] = P[k];
        }
        __syncthreads();

#pragma unroll
        for (int k = 0; k < 4; k++) {
            int q = t + 256 * k;
            P[k] = xg4[(b0 + 32 + (q >> 5)) * 4096 + c0 * 4 + (q & 31)];
        }
#pragma unroll
        for (int k = 0; k < 4; k++)
            *(float4*)&XA[k * 4] = *(const float4*)&xs[l * XS_STRIDE + w * 16 + k * 4];
        __syncthreads();

#pragma unroll
        for (int k = 0; k < 4; k++) {
            int q = t + 256 * k;
            *(float4*)&xs[(q >> 5) * XS_STRIDE + (q & 31) * 4] = P[k];
        }
        __syncthreads();
#pragma unroll
        for (int k = 0; k < 4; k++)
            *(float4*)&XB[k * 4] = *(const float4*)&xs[l * XS_STRIDE + w * 16 + k * 4];

#pragma unroll
        for (int nn = 0; nn < K1_NP; nn++) {
            const float* wsc = ws + nn * 2048 + w * 256;
            const int n = n_base + nn;

            u64 acc0[8], acc1[8];
#pragma unroll
            for (int dp = 0; dp < 8; dp++) { acc0[dp] = 0ULL; acc1[dp] = 0ULL; }
#pragma unroll
            for (int i = 0; i < 16; i++) {
                ulonglong2 wa = *(const ulonglong2*)&wsc[i * 16 + 0];
                ulonglong2 wb2 = *(const ulonglong2*)&wsc[i * 16 + 4];
                ulonglong2 wc = *(const ulonglong2*)&wsc[i * 16 + 8];
                ulonglong2 wd = *(const ulonglong2*)&wsc[i * 16 + 12];
                u64 xa = f2dup(XA[i]);
                u64 xb = f2dup(XB[i]);
                acc0[0] = f2fma(xa, wa.x, acc0[0]); acc0[1] = f2fma(xa, wa.y, acc0[1]);
                acc0[2] = f2fma(xa, wb2.x, acc0[2]); acc0[3] = f2fma(xa, wb2.y, acc0[3]);
                acc0[4] = f2fma(xa, wc.x, acc0[4]); acc0[5] = f2fma(xa, wc.y, acc0[5]);
                acc0[6] = f2fma(xa, wd.x, acc0[6]); acc0[7] = f2fma(xa, wd.y, acc0[7]);
                acc1[0] = f2fma(xb, wa.x, acc1[0]); acc1[1] = f2fma(xb, wa.y, acc1[1]);
                acc1[2] = f2fma(xb, wb2.x, acc1[2]); acc1[3] = f2fma(xb, wb2.y, acc1[3]);
                acc1[4] = f2fma(xb, wc.x, acc1[4]); acc1[5] = f2fma(xb, wc.y, acc1[5]);
                acc1[6] = f2fma(xb, wd.x, acc1[6]); acc1[7] = f2fma(xb, wd.y, acc1[7]);
            }

            if (p == 0 && nn == 0) {
#pragma unroll
                for (int k = 0; k < 4; k++) {
                    int q = t + 256 * k;
                    P[k] = xg4[(64 + (q >> 5)) * 4096 + c0 * 4 + (q & 31)];
                }
            }

#pragma unroll
            for (int dp = 0; dp < 8; dp++) {
                float2 f0 = *(float2*)&acc0[dp];
                float2 f1 = *(float2*)&acc1[dp];
                red[(0 * 8 + w) * RED_STRIDE + l * 9 + dp] =
                    h2_bits(__floats2half2_rn(f0.x, f0.y));
                red[(1 * 8 + w) * RED_STRIDE + l * 9 + dp] =
                    h2_bits(__floats2half2_rn(f1.x, f1.y));
            }
            __syncthreads();

#pragma unroll
            for (int k = 0; k < 4; k++) {
                int q = t + 256 * k;
                int hf = q >> 9;
                int qq = q & 511;
                int b_loc = qq >> 4;
                int ch    = qq & 15;
                int c_loc = ch >> 1;
                int dh    = ch & 1;
                const u32* rp = &red[(hf * 8 + c_loc) * RED_STRIDE + b_loc * 9 + dh * 4];
                uint4 v = make_uint4(rp[0], rp[1], rp[2], rp[3]);
                size_t gi = ((size_t)((b0 + hf * 32 + b_loc) * 16 + n) * 1024
                             + c0 + c_loc) * 2 + dh;
                ug[gi] = v;
            }

            {
                const int b2 = t >> 3, dp2 = t & 7;
#pragma unroll
                for (int hh = 0; hh < 2; hh++) {
                    float s0 = 0.f, s1 = 0.f;
#pragma unroll
                    for (int w2 = 0; w2 < 8; w2++) {
                        __half2 hv = *(__half2*)&red[(hh * 8 + w2) * RED_STRIDE + b2 * 9 + dp2];
                        float2 f = __half22float2(hv);
                        s0 += f.x; s1 += f.y;
                    }
                    *(float2*)&g_part[cblk * 32768 + (b0 + hh * 32 + b2) * 256
                                      + n * 16 + dp2 * 2] = make_float2(s0, s1);
                }
            }
            __syncthreads();
        }
    }
}

// ---------------------------------------------------------------------------
// k_usum stage 1: grid (128 b, 8), 256 threads
// ---------------------------------------------------------------------------
__global__ __launch_bounds__(256) void k_usum1() {
    const int t = threadIdx.x, b = blockIdx.x, cs = blockIdx.y;
    const float* p = g_part + (size_t)cs * 16 * 32768 + b * 256 + t;
    float a0 = 0, a1 = 0, a2 = 0, a3 = 0;
#pragma unroll
    for (int k = 0; k < 16; k += 4) {
        a0 += p[(size_t)(k + 0) * 32768];
        a1 += p[(size_t)(k + 1) * 32768];
        a2 += p[(size_t)(k + 2) * 32768];
        a3 += p[(size_t)(k + 3) * 32768];
    }
    g_us2[(size_t)cs * 32768 + b * 256 + t] = (a0 + a1) + (a2 + a3);
}

// ---------------------------------------------------------------------------
// k_usum stage 2: grid 128
// ---------------------------------------------------------------------------
__global__ __launch_bounds__(256) void k_usum2() {
    const int t = threadIdx.x, b = blockIdx.x;
    const float* p = g_us2 + b * 256 + t;
    float a0 = 0, a1 = 0, a2 = 0, a3 = 0;
#pragma unroll
    for (int k = 0; k < 8; k += 4) {
        a0 += p[(size_t)(k + 0) * 32768];
        a1 += p[(size_t)(k + 1) * 32768];
        a2 += p[(size_t)(k + 2) * 32768];
        a3 += p[(size_t)(k + 3) * 32768];
    }
    g_usum[b * 256 + t] = (a0 + a1) + (a2 + a3);
}

// ---------------------------------------------------------------------------
// k2a REWRITE: grid (128 b, 16 csplit), 256 threads, 2 tiles of 32 c.
// Register-resident u_hat: thread (sn, scs) owns n=sn, c in {scs, scs+16}.
// No smem u tile; scores AND accumulate use the same register copy.
// Final 16-way c-thread reduce via stride-20 smem buffer.
// ---------------------------------------------------------------------------
__global__ __launch_bounds__(256) void k2a_route(const float* __restrict__ Bb) {
    __shared__ float sco[544];           // [c][17]
    __shared__ float wbf[544];
    __shared__ float redbuf[256 * 20];   // [(sn*16+scs)*20 + d], 20.5 KB

    const int t  = threadIdx.x;
    const int b  = blockIdx.x;
    const int cs = blockIdx.y;
    const int sn = t >> 4, scs = t & 15;

    float ur[16];
#pragma unroll
    for (int j = 0; j < 16; j++) ur[j] = g_usum[b * 256 + sn * 16 + j];

    float sacc[16];
#pragma unroll
    for (int j = 0; j < 16; j++) sacc[j] = 0.f;

    const uint4* ug = (const uint4*)g_uhat;
    const size_t rowb = (size_t)(b * 16 + sn) * 2048;   // uint4 units

    // prefetch tile 0: u[b][sn][c][0..15] for c = cb+scs, cb+scs+16
    uint4 ca0, ca1, cb0, cb1;
    {
        const int cb = cs * 64;
        ca0 = ug[rowb + (cb + scs) * 2 + 0];
        ca1 = ug[rowb + (cb + scs) * 2 + 1];
        cb0 = ug[rowb + (cb + scs + 16) * 2 + 0];
        cb1 = ug[rowb + (cb + scs + 16) * 2 + 1];
    }

#pragma unroll
    for (int tile = 0; tile < K2_TILES; tile++) {
        const int cb = cs * 64 + tile * K2_CT;

        // prefetch next tile (overlaps dot/softmax)
        uint4 na0, na1, nb0, nb1;
        if (tile + 1 < K2_TILES) {
            const int cbn = cb + K2_CT;
            na0 = ug[rowb + (cbn + scs) * 2 + 0];
            na1 = ug[rowb + (cbn + scs) * 2 + 1];
            nb0 = ug[rowb + (cbn + scs + 16) * 2 + 0];
            nb1 = ug[rowb + (cbn + scs + 16) * 2 + 1];
        }

        // --- scores: dot(u[n][c], usum[n]) for both c
        float dot1 = 0.f, dot2 = 0.f;
        {
            const __half2* h1a = (const __half2*)&ca0;
            const __half2* h1b = (const __half2*)&ca1;
            const __half2* h2a = (const __half2*)&cb0;
            const __half2* h2b = (const __half2*)&cb1;
#pragma unroll
            for (int j = 0; j < 4; j++) {
                float2 f1a = __half22float2(h1a[j]);
                float2 f1b = __half22float2(h1b[j]);
                float2 f2a = __half22float2(h2a[j]);
                float2 f2b = __half22float2(h2b[j]);
                dot1 += f1a.x * ur[2 * j] + f1a.y * ur[2 * j + 1];
                dot1 += f1b.x * ur[8 + 2 * j] + f1b.y * ur[9 + 2 * j];
                dot2 += f2a.x * ur[2 * j] + f2a.y * ur[2 * j + 1];
                dot2 += f2b.x * ur[8 + 2 * j] + f2b.y * ur[9 + 2 * j];
            }
        }
        sco[scs * 17 + sn] = COEF * dot1;
        sco[(scs + 16) * 17 + sn] = COEF * dot2;
        __syncthreads();

        // --- softmax over n (per c) + add B
        if (t < 32) {
            int cx = t;
            float v[16];
            float m = -1e30f;
#pragma unroll
            for (int nn = 0; nn < 16; nn++) { v[nn] = sco[cx * 17 + nn]; m = fmaxf(m, v[nn]); }
            float s = 0.f;
#pragma unroll
            for (int nn = 0; nn < 16; nn++) { v[nn] = expf(v[nn] - m); s += v[nn]; }
            float inv = 1.0f / s;
#pragma unroll
            for (int nn = 0; nn < 16; nn++)
                wbf[cx * 17 + nn] = v[nn] * inv + Bb[nn * 1024 + cb + cx];
        }
        __syncthreads();

        // --- accumulate from the SAME registers
        {
            float w1 = wbf[scs * 17 + sn];
            float w2 = wbf[(scs + 16) * 17 + sn];
            const __half2* h1a = (const __half2*)&ca0;
            const __half2* h1b = (const __half2*)&ca1;
            const __half2* h2a = (const __half2*)&cb0;
            const __half2* h2b = (const __half2*)&cb1;
#pragma unroll
            for (int j = 0; j < 4; j++) {
                float2 f1a = __half22float2(h1a[j]);
                float2 f1b = __half22float2(h1b[j]);
                float2 f2a = __half22float2(h2a[j]);
                float2 f2b = __half22float2(h2b[j]);
                sacc[2 * j]     += w1 * f1a.x + w2 * f2a.x;
                sacc[2 * j + 1] += w1 * f1a.y + w2 * f2a.y;
                sacc[8 + 2 * j] += w1 * f1b.x + w2 * f2b.x;
                sacc[9 + 2 * j] += w1 * f1b.y + w2 * f2b.y;
            }
        }

        // rotate prefetched tile in
        if (tile + 1 < K2_TILES) { ca0 = na0; ca1 = na1; cb0 = nb0; cb1 = nb1; }
    }

    // --- final reduce over the 16 c-threads per n (stride-20: conflict-free STS.128)
    {
        float* rb = &redbuf[t * 20];
        *(float4*)(rb + 0)  = make_float4(sacc[0], sacc[1], sacc[2], sacc[3]);
        *(float4*)(rb + 4)  = make_float4(sacc[4], sacc[5], sacc[6], sacc[7]);
        *(float4*)(rb + 8)  = make_float4(sacc[8], sacc[9], sacc[10], sacc[11]);
        *(float4*)(rb + 12) = make_float4(sacc[12], sacc[13], sacc[14], sacc[15]);
    }
    __syncthreads();
    {
        const int n = t >> 4, d = t & 15;
        float s = 0.f;
#pragma unroll
        for (int c2 = 0; c2 < 16; c2++) s += redbuf[(n * 16 + c2) * 20 + d];
        g_spart[cs * 32768 + b * 256 + t] = s;
    }
}

// ---------------------------------------------------------------------------
// k2b: reduce 16 csplits, squash, write out
// ---------------------------------------------------------------------------
__global__ __launch_bounds__(256) void k2b_finish(float* __restrict__ out) {
    __shared__ float sfin[256];
    __shared__ float scale[16];
    const int t = threadIdx.x, b = blockIdx.x;

    const float* p = g_spart + b * 256 + t;
    float a0 = 0, a1 = 0, a2 = 0, a3 = 0;
#pragma unroll
    for (int k = 0; k < K2_SPLIT; k += 4) {
        a0 += p[(k + 0) * 32768];
        a1 += p[(k + 1) * 32768];
        a2 += p[(k + 2) * 32768];
        a3 += p[(k + 3) * 32768];
    }
    sfin[t] = (a0 + a1) + (a2 + a3);
    __syncthreads();

    if (t < 16) {
        float sq = 0.f;
#pragma unroll
        for (int d = 0; d < 16; d++) { float z = sfin[t * 16 + d]; sq += z * z; }
        float norm = sqrtf(sq);
        scale[t] = (1.0f - expf(-norm)) * rsqrtf(sq + 1e-8f);
    }
    __syncthreads();

    out[b * 256 + t] = scale[t >> 4] * sfin[t];
}

// ---------------------------------------------------------------------------
extern "C" void kernel_launch(void* const* d_in, const int* in_sizes, int n_in,
                              void* d_out, int out_size) {
    const float* x = (const float*)d_in[0];
    const float* W = (const float*)d_in[1];
    const float* B = (const float*)d_in[2];
    float* out = (float*)d_out;

    cudaFuncSetAttribute(k1_uhat, cudaFuncAttributeMaxDynamicSharedMemorySize,
                         K1_SMEM_BYTES);

    k1_uhat<<<dim3(K1_NCBLK, K1_NP), 256, K1_SMEM_BYTES>>>(x, W);
    k_usum1<<<dim3(BATCH, 8), 256>>>();
    k_usum2<<<BATCH, 256>>>();
    k2a_route<<<dim3(BATCH, K2_SPLIT), 256>>>(B);
    k2b_finish<<<BATCH, 256>>>(out);
}

// round 16
// speedup vs baseline: 1.0556x; 1.0556x over previous
#include <cuda_runtime.h>
#include <cuda_fp16.h>

// DigitCaps routing:
//   x [128,1024,16], W [1,16,1024,16,16], B [16,1,1024] -> out [128,16,16] (fp32)
// Measured: k1 ~45.7us, k2a 29.8 (smem) / 31.7 (reg+2tile), usum ~5.5, k2b 5.
// R16: k1 double-buffered red (1 sync/nn); k2a register-resident SINGLE-tile
//      (split 32, no prefetch regs).

#define BATCH  128
#define NCAPS  16
#define INCAPS 1024
#define DIMC   16
#define COEF   0.25f

#define K1_CB     8
#define K1_NCBLK  128
#define K1_NP     4      // n per CTA
#define K2_CT     32
#define K2_SPLIT  32     // one 32-c tile per CTA

#define RED_STRIDE 289   // u32 row stride
#define XS_STRIDE  132   // float row stride (128 + 4 pad)

// k1 dynamic smem layout (bytes)
#define K1_WS_BYTES   (K1_NP * 2048 * 4)              // 32768
#define K1_XS_BYTES   (32 * XS_STRIDE * 4)            // 16896
#define K1_RED_BYTES  (2 * 2 * 8 * RED_STRIDE * 4)    // 36992 (double-buffered)
#define K1_SMEM_BYTES (K1_WS_BYTES + K1_XS_BYTES + K1_RED_BYTES)  // 86656

typedef unsigned long long u64;
typedef unsigned int u32;

__device__ __forceinline__ u64 f2fma(u64 a, u64 b, u64 c) {
    u64 d;
    asm("fma.rn.f32x2 %0, %1, %2, %3;" : "=l"(d) : "l"(a), "l"(b), "l"(c));
    return d;
}
__device__ __forceinline__ u64 f2dup(float x) {
    u64 d;
    asm("mov.b64 %0, {%1, %1};" : "=l"(d) : "f"(x));
    return d;
}
__device__ __forceinline__ u32 h2_bits(__half2 h) {
    union { __half2 h; u32 u; } cv;
    cv.h = h;
    return cv.u;
}

// scratch
__device__ __half g_uhat[(size_t)BATCH * NCAPS * INCAPS * DIMC];    // 64 MB
__device__ float  g_part[(size_t)K1_NCBLK * BATCH * NCAPS * DIMC];  // 16 MB
__device__ float  g_us2[(size_t)8 * BATCH * NCAPS * DIMC];          // 1 MB
__device__ float  g_usum[(size_t)BATCH * NCAPS * DIMC];             // 128 KB
__device__ float  g_spart[(size_t)K2_SPLIT * BATCH * NCAPS * DIMC]; // 4 MB

// ---------------------------------------------------------------------------
// Kernel 1: grid (128 cblk, 4 ngrp), 256 threads, 4 n per CTA.
// Double-buffered red: one sync per nn; drain(nn) overlaps compute(nn+1).
// ---------------------------------------------------------------------------
__global__ __launch_bounds__(256, 2) void k1_uhat(const float* __restrict__ x,
                                                  const float* __restrict__ W) {
    extern __shared__ char smem_raw[];
    float* ws  = (float*)smem_raw;                               // [nn][cl][i][d]
    float* xs  = (float*)(smem_raw + K1_WS_BYTES);               // staging
    u32*   red = (u32*)(smem_raw + K1_WS_BYTES + K1_XS_BYTES);   // [buf][hf][cl][...]

    const int t = threadIdx.x;
    const int w = t >> 5;
    const int l = t & 31;
    const int cblk   = blockIdx.x;
    const int n_base = blockIdx.y * K1_NP;
    const int c0     = cblk * K1_CB;

    // --- load 4 W tiles, transposing [c][d][i] -> [nn][c][i][d]
    const float4* Wg4 = (const float4*)W;
#pragma unroll
    for (int k = 0; k < 8; k++) {
        int idx4 = t + 256 * k;
        int nn  = idx4 >> 9;
        int rem = idx4 & 511;
        float4 v = Wg4[(size_t)(n_base + nn) * 65536 + c0 * 64 + rem];
        int cl = rem >> 6;
        int d  = (rem >> 2) & 15;
        int i0 = (rem & 3) * 4;
        float* wb = ws + nn * 2048 + cl * 256;
        wb[(i0 + 0) * 16 + d] = v.x;
        wb[(i0 + 1) * 16 + d] = v.y;
        wb[(i0 + 2) * 16 + d] = v.z;
        wb[(i0 + 3) * 16 + d] = v.w;
    }

    const float4* xg4 = (const float4*)x;
    uint4* ug = (uint4*)g_uhat;

    float4 P[4];
#pragma unroll
    for (int k = 0; k < 4; k++) {
        int q = t + 256 * k;
        P[k] = xg4[(q >> 5) * 4096 + c0 * 4 + (q & 31)];
    }

    float XA[16], XB[16];

#pragma unroll
    for (int p = 0; p < 2; p++) {
        const int b0 = p * 64;

        // ---- stage half0
#pragma unroll
        for (int k = 0; k < 4; k++) {
            int q = t + 256 * k;
            *(float4*)&xs[(q >> 5) * XS_STRIDE + (q & 31) * 4] = P[k];
        }
        __syncthreads();                       // xs half0 (and ws on p=0) ready

#pragma unroll
        for (int k = 0; k < 4; k++) {
            int q = t + 256 * k;
            P[k] = xg4[(b0 + 32 + (q >> 5)) * 4096 + c0 * 4 + (q & 31)];
        }
#pragma unroll
        for (int k = 0; k < 4; k++)
            *(float4*)&XA[k * 4] = *(const float4*)&xs[l * XS_STRIDE + w * 16 + k * 4];
        __syncthreads();                       // XA reads done

        // ---- stage half1
#pragma unroll
        for (int k = 0; k < 4; k++) {
            int q = t + 256 * k;
            *(float4*)&xs[(q >> 5) * XS_STRIDE + (q & 31) * 4] = P[k];
        }
        __syncthreads();                       // xs half1 ready
#pragma unroll
        for (int k = 0; k < 4; k++)
            *(float4*)&XB[k * 4] = *(const float4*)&xs[l * XS_STRIDE + w * 16 + k * 4];

        // ---- n loop: 1 sync per nn, double-buffered red
#pragma unroll
        for (int nn = 0; nn < K1_NP; nn++) {
            const float* wsc = ws + nn * 2048 + w * 256;
            const int n = n_base + nn;
            u32* redb = red + (nn & 1) * (16 * RED_STRIDE);

            u64 acc0[8], acc1[8];
#pragma unroll
            for (int dp = 0; dp < 8; dp++) { acc0[dp] = 0ULL; acc1[dp] = 0ULL; }
#pragma unroll
            for (int i = 0; i < 16; i++) {
                ulonglong2 wa = *(const ulonglong2*)&wsc[i * 16 + 0];
                ulonglong2 wb2 = *(const ulonglong2*)&wsc[i * 16 + 4];
                ulonglong2 wc = *(const ulonglong2*)&wsc[i * 16 + 8];
                ulonglong2 wd = *(const ulonglong2*)&wsc[i * 16 + 12];
                u64 xa = f2dup(XA[i]);
                u64 xb = f2dup(XB[i]);
                acc0[0] = f2fma(xa, wa.x, acc0[0]); acc0[1] = f2fma(xa, wa.y, acc0[1]);
                acc0[2] = f2fma(xa, wb2.x, acc0[2]); acc0[3] = f2fma(xa, wb2.y, acc0[3]);
                acc0[4] = f2fma(xa, wc.x, acc0[4]); acc0[5] = f2fma(xa, wc.y, acc0[5]);
                acc0[6] = f2fma(xa, wd.x, acc0[6]); acc0[7] = f2fma(xa, wd.y, acc0[7]);
                acc1[0] = f2fma(xb, wa.x, acc1[0]); acc1[1] = f2fma(xb, wa.y, acc1[1]);
                acc1[2] = f2fma(xb, wb2.x, acc1[2]); acc1[3] = f2fma(xb, wb2.y, acc1[3]);
                acc1[4] = f2fma(xb, wc.x, acc1[4]); acc1[5] = f2fma(xb, wc.y, acc1[5]);
                acc1[6] = f2fma(xb, wd.x, acc1[6]); acc1[7] = f2fma(xb, wd.y, acc1[7]);
            }

            if (p == 0 && nn == 0) {
#pragma unroll
                for (int k = 0; k < 4; k++) {
                    int q = t + 256 * k;
                    P[k] = xg4[(64 + (q >> 5)) * 4096 + c0 * 4 + (q & 31)];
                }
            }

            // stage accs into this nn's buffer
#pragma unroll
            for (int dp = 0; dp < 8; dp++) {
                float2 f0 = *(float2*)&acc0[dp];
                float2 f1 = *(float2*)&acc1[dp];
                redb[(0 * 8 + w) * RED_STRIDE + l * 9 + dp] =
                    h2_bits(__floats2half2_rn(f0.x, f0.y));
                redb[(1 * 8 + w) * RED_STRIDE + l * 9 + dp] =
                    h2_bits(__floats2half2_rn(f1.x, f1.y));
            }
            __syncthreads();   // redb ready; also: prev drain (other buf) done

            // consumer A: coalesced u_hat store (1024 uint4, 4/thread)
#pragma unroll
            for (int k = 0; k < 4; k++) {
                int q = t + 256 * k;
                int hf = q >> 9;
                int qq = q & 511;
                int b_loc = qq >> 4;
                int ch    = qq & 15;
                int c_loc = ch >> 1;
                int dh    = ch & 1;
                const u32* rp = &redb[(hf * 8 + c_loc) * RED_STRIDE + b_loc * 9 + dh * 4];
                uint4 v = make_uint4(rp[0], rp[1], rp[2], rp[3]);
                size_t gi = ((size_t)((b0 + hf * 32 + b_loc) * 16 + n) * 1024
                             + c0 + c_loc) * 2 + dh;
                ug[gi] = v;
            }

            // consumer B: c-partials -> g_part
            {
                const int b2 = t >> 3, dp2 = t & 7;
#pragma unroll
                for (int hh = 0; hh < 2; hh++) {
                    float s0 = 0.f, s1 = 0.f;
#pragma unroll
                    for (int w2 = 0; w2 < 8; w2++) {
                        __half2 hv = *(__half2*)&redb[(hh * 8 + w2) * RED_STRIDE + b2 * 9 + dp2];
                        float2 f = __half22float2(hv);
                        s0 += f.x; s1 += f.y;
                    }
                    *(float2*)&g_part[cblk * 32768 + (b0 + hh * 32 + b2) * 256
                                      + n * 16 + dp2 * 2] = make_float2(s0, s1);
                }
            }
            // no trailing sync: next nn writes the OTHER red buffer; the sync
            // inside nn+1 orders reuse of this one two iterations later.
        }
    }
}

// ---------------------------------------------------------------------------
// k_usum stage 1: grid (128 b, 8), 256 threads
// ---------------------------------------------------------------------------
__global__ __launch_bounds__(256) void k_usum1() {
    const int t = threadIdx.x, b = blockIdx.x, cs = blockIdx.y;
    const float* p = g_part + (size_t)cs * 16 * 32768 + b * 256 + t;
    float a0 = 0, a1 = 0, a2 = 0, a3 = 0;
#pragma unroll
    for (int k = 0; k < 16; k += 4) {
        a0 += p[(size_t)(k + 0) * 32768];
        a1 += p[(size_t)(k + 1) * 32768];
        a2 += p[(size_t)(k + 2) * 32768];
        a3 += p[(size_t)(k + 3) * 32768];
    }
    g_us2[(size_t)cs * 32768 + b * 256 + t] = (a0 + a1) + (a2 + a3);
}

// ---------------------------------------------------------------------------
// k_usum stage 2: grid 128
// ---------------------------------------------------------------------------
__global__ __launch_bounds__(256) void k_usum2() {
    const int t = threadIdx.x, b = blockIdx.x;
    const float* p = g_us2 + b * 256 + t;
    float a0 = 0, a1 = 0, a2 = 0, a3 = 0;
#pragma unroll
    for (int k = 0; k < 8; k += 4) {
        a0 += p[(size_t)(k + 0) * 32768];
        a1 += p[(size_t)(k + 1) * 32768];
        a2 += p[(size_t)(k + 2) * 32768];
        a3 += p[(size_t)(k + 3) * 32768];
    }
    g_usum[b * 256 + t] = (a0 + a1) + (a2 + a3);
}

// ---------------------------------------------------------------------------
// k2a: grid (128 b, 32 csplit), 256 threads, ONE 32-c tile per CTA.
// Register-resident u_hat; thread (sn, scs) owns n=sn, c in {scs, scs+16}.
// ---------------------------------------------------------------------------
__global__ __launch_bounds__(256) void k2a_route(const float* __restrict__ Bb) {
    __shared__ float sco[544];           // [c][17]
    __shared__ float wbf[544];
    __shared__ float redbuf[256 * 20];   // 20.5 KB

    const int t  = threadIdx.x;
    const int b  = blockIdx.x;
    const int cs = blockIdx.y;
    const int sn = t >> 4, scs = t & 15;
    const int cb = cs * K2_CT;

    float ur[16];
#pragma unroll
    for (int j = 0; j < 16; j++) ur[j] = g_usum[b * 256 + sn * 16 + j];

    const uint4* ug = (const uint4*)g_uhat;
    const size_t rowb = (size_t)(b * 16 + sn) * 2048;   // uint4 units

    // load this CTA's tile: u[b][sn][c][0..15] for c = cb+scs, cb+scs+16
    uint4 ca0 = ug[rowb + (cb + scs) * 2 + 0];
    uint4 ca1 = ug[rowb + (cb + scs) * 2 + 1];
    uint4 cb0 = ug[rowb + (cb + scs + 16) * 2 + 0];
    uint4 cb1 = ug[rowb + (cb + scs + 16) * 2 + 1];

    // --- scores
    float dot1 = 0.f, dot2 = 0.f;
    {
        const __half2* h1a = (const __half2*)&ca0;
        const __half2* h1b = (const __half2*)&ca1;
        const __half2* h2a = (const __half2*)&cb0;
        const __half2* h2b = (const __half2*)&cb1;
#pragma unroll
        for (int j = 0; j < 4; j++) {
            float2 f1a = __half22float2(h1a[j]);
            float2 f1b = __half22float2(h1b[j]);
            float2 f2a = __half22float2(h2a[j]);
            float2 f2b = __half22float2(h2b[j]);
            dot1 += f1a.x * ur[2 * j] + f1a.y * ur[2 * j + 1];
            dot1 += f1b.x * ur[8 + 2 * j] + f1b.y * ur[9 + 2 * j];
            dot2 += f2a.x * ur[2 * j] + f2a.y * ur[2 * j + 1];
            dot2 += f2b.x * ur[8 + 2 * j] + f2b.y * ur[9 + 2 * j];
        }
    }
    sco[scs * 17 + sn] = COEF * dot1;
    sco[(scs + 16) * 17 + sn] = COEF * dot2;
    __syncthreads();

    // --- softmax over n (per c) + add B
    if (t < 32) {
        int cx = t;
        float v[16];
        float m = -1e30f;
#pragma unroll
        for (int nn = 0; nn < 16; nn++) { v[nn] = sco[cx * 17 + nn]; m = fmaxf(m, v[nn]); }
        float s = 0.f;
#pragma unroll
        for (int nn = 0; nn < 16; nn++) { v[nn] = expf(v[nn] - m); s += v[nn]; }
        float inv = 1.0f / s;
#pragma unroll
        for (int nn = 0; nn < 16; nn++)
            wbf[cx * 17 + nn] = v[nn] * inv + Bb[nn * 1024 + cb + cx];
    }
    __syncthreads();

    // --- weighted accumulate from the same registers
    float sacc[16];
    {
        float w1 = wbf[scs * 17 + sn];
        float w2 = wbf[(scs + 16) * 17 + sn];
        const __half2* h1a = (const __half2*)&ca0;
        const __half2* h1b = (const __half2*)&ca1;
        const __half2* h2a = (const __half2*)&cb0;
        const __half2* h2b = (const __half2*)&cb1;
#pragma unroll
        for (int j = 0; j < 4; j++) {
            float2 f1a = __half22float2(h1a[j]);
            float2 f1b = __half22float2(h1b[j]);
            float2 f2a = __half22float2(h2a[j]);
            float2 f2b = __half22float2(h2b[j]);
            sacc[2 * j]     = w1 * f1a.x + w2 * f2a.x;
            sacc[2 * j + 1] = w1 * f1a.y + w2 * f2a.y;
            sacc[8 + 2 * j] = w1 * f1b.x + w2 * f2b.x;
            sacc[9 + 2 * j] = w1 * f1b.y + w2 * f2b.y;
        }
    }

    // --- reduce over the 16 c-threads per n
    {
        float* rb = &redbuf[t * 20];
        *(float4*)(rb + 0)  = make_float4(sacc[0], sacc[1], sacc[2], sacc[3]);
        *(float4*)(rb + 4)  = make_float4(sacc[4], sacc[5], sacc[6], sacc[7]);
        *(float4*)(rb + 8)  = make_float4(sacc[8], sacc[9], sacc[10], sacc[11]);
        *(float4*)(rb + 12) = make_float4(sacc[12], sacc[13], sacc[14], sacc[15]);
    }
    __syncthreads();
    {
        const int n = t >> 4, d = t & 15;
        float s = 0.f;
#pragma unroll
        for (int c2 = 0; c2 < 16; c2++) s += redbuf[(n * 16 + c2) * 20 + d];
        g_spart[(size_t)cs * 32768 + b * 256 + t] = s;
    }
}

// ---------------------------------------------------------------------------
// k2b: reduce 32 csplits, squash, write out
// ---------------------------------------------------------------------------
__global__ __launch_bounds__(256) void k2b_finish(float* __restrict__ out) {
    __shared__ float sfin[256];
    __shared__ float scale[16];
    const int t = threadIdx.x, b = blockIdx.x;

    const float* p = g_spart + b * 256 + t;
    float a0 = 0, a1 = 0, a2 = 0, a3 = 0;
#pragma unroll
    for (int k = 0; k < K2_SPLIT; k += 4) {
        a0 += p[(size_t)(k + 0) * 32768];
        a1 += p[(size_t)(k + 1) * 32768];
        a2 += p[(size_t)(k + 2) * 32768];
        a3 += p[(size_t)(k + 3) * 32768];
    }
    sfin[t] = (a0 + a1) + (a2 + a3);
    __syncthreads();

    if (t < 16) {
        float sq = 0.f;
#pragma unroll
        for (int d = 0; d < 16; d++) { float z = sfin[t * 16 + d]; sq += z * z; }
        float norm = sqrtf(sq);
        scale[t] = (1.0f - expf(-norm)) * rsqrtf(sq + 1e-8f);
    }
    __syncthreads();

    out[b * 256 + t] = scale[t >> 4] * sfin[t];
}

// ---------------------------------------------------------------------------
extern "C" void kernel_launch(void* const* d_in, const int* in_sizes, int n_in,
                              void* d_out, int out_size) {
    const float* x = (const float*)d_in[0];
    const float* W = (const float*)d_in[1];
    const float* B = (const float*)d_in[2];
    float* out = (float*)d_out;

    cudaFuncSetAttribute(k1_uhat, cudaFuncAttributeMaxDynamicSharedMemorySize,
                         K1_SMEM_BYTES);

    k1_uhat<<<dim3(K1_NCBLK, K1_NP), 256, K1_SMEM_BYTES>>>(x, W);
    k_usum1<<<dim3(BATCH, 8), 256>>>();
    k_usum2<<<BATCH, 256>>>();
    k2a_route<<<dim3(BATCH, K2_SPLIT), 256>>>(B);
    k2b_finish<<<BATCH, 256>>>(out);
}